// round 9
// baseline (speedup 1.0000x reference)
#include <cuda_runtime.h>
#include <cuda_bf16.h>
#include <math.h>
#include <stdint.h>

// ---------------- problem constants ----------------
#define BB   4
#define TT   1024
#define HID  1024
#define NA   1024
#define CTX  1024
#define NC   32
#define CL   32

// ---------------- GEMM tiling ----------------
// CTA tile 256(M) x 128(N), K-chunk 64, 8 warps, warp tile 64x64.
#define ATILE_F 8192        // one 128x64 tf32 tile = 8192 floats = 32KB
#define STG     98304       // stage: 2 A tiles + 1 B tile = 96KB
#define SMEMT   (1024 + 2*STG)

// ---------------- static scratch ----------------
__device__ float g_k[BB*TT*NA];
__device__ float g_v[BB*TT*NA];
__device__ float g_r[BB*TT*NA];
__device__ float g_Send[BB*NC*NA];
__device__ float g_Ksum[BB*NC*NA];
// tf32 fragment-packed operands (A reused: xs for KVR, then rwkv for Wo)
__device__ __align__(16) float g_Atf[BB*TT*HID];   // 512 tiles of 128x64
__device__ __align__(16) float g_Wtf[4*HID*NA];    // 4 weights x 128 tiles

// ---------------- ptx helpers (baseline features only) ----------------
__device__ __forceinline__ uint32_t smem_u32(const void* p) {
    uint32_t a;
    asm("{ .reg .u64 t; cvta.to.shared.u64 t, %1; cvt.u32.u64 %0, t; }" : "=r"(a) : "l"(p));
    return a;
}
#define MBAR_INIT(a, c) \
    asm volatile("mbarrier.init.shared.b64 [%0], %1;" :: "r"(a), "r"(c) : "memory")
#define MBAR_EXPECT_TX(a, b) \
    asm volatile("mbarrier.arrive.expect_tx.shared.b64 _, [%0], %1;" :: "r"(a), "r"(b) : "memory")
#define MBAR_ARRIVE(a) \
    asm volatile("mbarrier.arrive.shared.b64 _, [%0];" :: "r"(a) : "memory")
#define MBAR_WAIT(a, ph) do { \
    asm volatile("{\n\t.reg .pred P;\n\tWL%=:\n\t" \
        "mbarrier.try_wait.parity.acquire.cta.shared::cta.b64 P, [%0], %1, 0x989680;\n\t" \
        "@P bra.uni WD%=;\n\tbra.uni WL%=;\n\tWD%=:\n\t}" \
        :: "r"(a), "r"(ph) : "memory"); } while (0)

__device__ __forceinline__ void bulk_ldg(uint32_t dst, const void* src, uint32_t bytes, uint32_t mbar) {
    asm volatile("cp.async.bulk.shared::cluster.global.mbarrier::complete_tx::bytes [%0], [%1], %2, [%3];"
        :: "r"(dst), "l"((unsigned long long)__cvta_generic_to_global(src)), "r"(bytes), "r"(mbar) : "memory");
}
__device__ __forceinline__ void mma1688tf(float* d, const uint32_t* a, const uint32_t* b) {
    asm volatile("mma.sync.aligned.m16n8k8.row.col.f32.tf32.tf32.f32 "
        "{%0,%1,%2,%3}, {%4,%5,%6,%7}, {%8,%9}, {%0,%1,%2,%3};"
        : "+f"(d[0]), "+f"(d[1]), "+f"(d[2]), "+f"(d[3])
        : "r"(a[0]), "r"(a[1]), "r"(a[2]), "r"(a[3]), "r"(b[0]), "r"(b[1]));
}
__device__ __forceinline__ uint32_t tf32r(float v) {
    uint32_t r;
    asm("cvt.rna.tf32.f32 %0, %1;" : "=r"(r) : "f"(v));
    return r;
}
// x with RWKV time shift
__device__ __forceinline__ float ldx(const float* __restrict__ x, int m, int k) {
    const int t = m & (TT - 1);
    if (k < HID / 2) return (t > 0) ? x[(size_t)(m - 1) * HID + k] : 0.f;
    return x[(size_t)m * HID + k];
}

// ---------------- merged conversion: xs -> A tiles, W* -> B tiles ----------------
// blockIdx.x < 4096: A path.  >= 4096: B path.
// A frag map (m16n8k8.tf32): a0=(m0,k0), a1=(m0+8,k0), a2=(m0,k0+4), a3=(m0+8,k0+4)
// B pair-packed: cell (gp=s*8+fp, l) = {b0(f=2fp), b1(f=2fp), b0(f=2fp+1), b1(f=2fp+1)}
__global__ __launch_bounds__(256)
void conv_all(const float* __restrict__ x,
              const float* __restrict__ Wk, const float* __restrict__ Wv,
              const float* __restrict__ Wr, const float* __restrict__ Wo)
{
    if (blockIdx.x < 4096) {
        const int idx = blockIdx.x * 256 + threadIdx.x;
        const int l = idx & 31;
        const int g = (idx >> 5) & 63;       // g = s*8 + mf
        const int tile = idx >> 11;          // tile = tm128*16 + tk
        const int tm = tile >> 4, tk = tile & 15;
        const int s = g >> 3, mf = g & 7;
        const int m0 = tm * 128 + mf * 16 + (l >> 2);
        const int k0 = tk * 64 + s * 8 + (l & 3);
        uint4 q;
        q.x = tf32r(ldx(x, m0,     k0));
        q.y = tf32r(ldx(x, m0 + 8, k0));
        q.z = tf32r(ldx(x, m0,     k0 + 4));
        q.w = tf32r(ldx(x, m0 + 8, k0 + 4));
        *(uint4*)(g_Atf + (size_t)tile * ATILE_F + (size_t)(g * 32 + l) * 4) = q;
    } else {
        const int idx = (blockIdx.x - 4096) * 256 + threadIdx.x;
        const int l = idx & 31;
        const int gp = (idx >> 5) & 63;      // gp = s*8 + fp
        const int tile = idx >> 11;          // tile = widx*128 + tn*16 + tk
        const int widx = tile >> 7;
        const int rem = tile & 127;
        const int tn = rem >> 4, tk = rem & 15;
        const int s = gp >> 3, fp = gp & 7;
        const int k0 = tk * 64 + s * 8 + (l & 3);
        const int ne = tn * 128 + fp * 16 + (l >> 2);
        const float* W = (widx == 0) ? Wk : (widx == 1) ? Wv : (widx == 2) ? Wr : Wo;
        uint4 q;
        q.x = tf32r(W[(size_t)k0 * NA + ne]);
        q.y = tf32r(W[(size_t)(k0 + 4) * NA + ne]);
        q.z = tf32r(W[(size_t)k0 * NA + ne + 8]);
        q.w = tf32r(W[(size_t)(k0 + 4) * NA + ne + 8]);
        *(uint4*)(g_Wtf + (size_t)tile * ATILE_F + (size_t)(gp * 32 + l) * 4) = q;
    }
}

// ---------------- tf32 GEMM: C[4096, 1024-slice] = A @ W (+bias, +act) ----------------
// CTA 256x128, warp tile 64x64.  widx: 0=K(exp-clip) 1=V 2=R(sigmoid) 3=Wo(*gamma, ->obuf)
__global__ __launch_bounds__(256, 1)
void gemm_tf(int widx_fixed,
             const float* __restrict__ bk, const float* __restrict__ bv,
             const float* __restrict__ br, const float* __restrict__ bo,
             const float* __restrict__ gamma, float* __restrict__ obuf)
{
    extern __shared__ char smem_raw[];
    char* smem_al = (char*)(((uintptr_t)smem_raw + 1023) & ~(uintptr_t)1023);
    const uint32_t sb = smem_u32(smem_al);
    const int tid = threadIdx.x, l = tid & 31, w = tid >> 5;
    const int wm = w & 3, wn = w >> 2;        // 4 M-warps x 2 N-warps
    int widx, tn;
    if (widx_fixed >= 0) { widx = widx_fixed; tn = blockIdx.x; }
    else                 { widx = blockIdx.x >> 3; tn = blockIdx.x & 7; }
    const int tm = blockIdx.y;                // 16 tiles of 256 rows

    if (tid == 0) {
        MBAR_INIT(sb + 0, 1);
        MBAR_INIT(sb + 8, 1);
        MBAR_INIT(sb + 64, 256);
        MBAR_INIT(sb + 72, 256);
    }
    __syncthreads();

    const float* A0 = g_Atf + ((size_t)(tm * 2)     * 16) * ATILE_F;
    const float* A1 = g_Atf + ((size_t)(tm * 2 + 1) * 16) * ATILE_F;
    const float* Bw = g_Wtf + ((size_t)(widx * 8 + tn) * 16) * ATILE_F;

    if (tid == 0) {
#pragma unroll
        for (int c = 0; c < 2; c++) {
            const uint32_t st = sb + 1024 + c * STG;
            MBAR_EXPECT_TX(sb + 8 * c, STG);
            bulk_ldg(st,         A0 + (size_t)c * ATILE_F, 32768, sb + 8 * c);
            bulk_ldg(st + 32768, A1 + (size_t)c * ATILE_F, 32768, sb + 8 * c);
            bulk_ldg(st + 65536, Bw + (size_t)c * ATILE_F, 32768, sb + 8 * c);
        }
    }

    float acc[4][8][4];
#pragma unroll
    for (int i = 0; i < 4; i++)
#pragma unroll
        for (int j = 0; j < 8; j++)
#pragma unroll
            for (int q = 0; q < 4; q++) acc[i][j][q] = 0.f;

    const uint32_t a_wbase = (uint32_t)(wm >> 1) * 32768 + ((uint32_t)(wm & 1) * 4 * 32 + l) * 16;
    const uint32_t b_wbase = 65536u + ((uint32_t)wn * 4 * 32 + l) * 16;

    for (int c = 0; c < 16; c++) {
        const int s = c & 1;
        const uint32_t par = (uint32_t)((c >> 1) & 1);
        MBAR_WAIT(sb + 8 * s, par);
        const char* stp = smem_al + 1024 + s * STG;
        const char* ap = stp + a_wbase;
        const char* bp = stp + b_wbase;
#pragma unroll 2
        for (int ks = 0; ks < 8; ks++) {
            uint4 Aq[4], Bq[4];
#pragma unroll
            for (int mt = 0; mt < 4; mt++)
                Aq[mt] = *(const uint4*)(ap + (uint32_t)(ks * 8 + mt) * 512);
#pragma unroll
            for (int ntp = 0; ntp < 4; ntp++)
                Bq[ntp] = *(const uint4*)(bp + (uint32_t)(ks * 8 + ntp) * 512);
#pragma unroll
            for (int mt = 0; mt < 4; mt++) {
                const uint32_t Af[4] = {Aq[mt].x, Aq[mt].y, Aq[mt].z, Aq[mt].w};
#pragma unroll
                for (int ntp = 0; ntp < 4; ntp++) {
                    const uint32_t B0[2] = {Bq[ntp].x, Bq[ntp].y};
                    const uint32_t B1[2] = {Bq[ntp].z, Bq[ntp].w};
                    mma1688tf(acc[mt][2 * ntp],     Af, B0);
                    mma1688tf(acc[mt][2 * ntp + 1], Af, B1);
                }
            }
        }
        MBAR_ARRIVE(sb + 64 + 8 * s);
        if (tid == 0 && c + 2 < 16) {
            MBAR_WAIT(sb + 64 + 8 * s, par);
            const int cc = c + 2;
            const uint32_t st = sb + 1024 + s * STG;
            MBAR_EXPECT_TX(sb + 8 * s, STG);
            bulk_ldg(st,         A0 + (size_t)cc * ATILE_F, 32768, sb + 8 * s);
            bulk_ldg(st + 32768, A1 + (size_t)cc * ATILE_F, 32768, sb + 8 * s);
            bulk_ldg(st + 65536, Bw + (size_t)cc * ATILE_F, 32768, sb + 8 * s);
        }
    }

    // ---- epilogue ----
    const float* bias = (widx == 0) ? bk : (widx == 1) ? bv : (widx == 2) ? br : bo;
    float* out = (widx == 0) ? g_k : (widx == 1) ? g_v : (widx == 2) ? g_r : obuf;
    const int mrow_base = tm * 256 + wm * 64;
    const int col_base  = tn * 128 + wn * 64;
#pragma unroll
    for (int mt = 0; mt < 4; mt++) {
#pragma unroll
        for (int nt = 0; nt < 8; nt++) {
            const int r0 = mrow_base + mt * 16 + (l >> 2);
            const int cb = col_base + nt * 8 + (l & 3) * 2;
            const float b0 = bias[cb], b1 = bias[cb + 1];
#pragma unroll
            for (int half = 0; half < 2; half++) {
                const int row = r0 + half * 8;
                float v0 = acc[mt][nt][half * 2]     + b0;
                float v1 = acc[mt][nt][half * 2 + 1] + b1;
                if (widx == 0) {
                    v0 = __expf(fminf(fmaxf(v0, -60.f), 30.f));
                    v1 = __expf(fminf(fmaxf(v1, -60.f), 30.f));
                } else if (widx == 2) {
                    v0 = __fdividef(1.f, 1.f + __expf(-v0));
                    v1 = __fdividef(1.f, 1.f + __expf(-v1));
                } else if (widx == 3) {
                    const float gm = gamma[row & (TT - 1)];
                    v0 *= gm; v1 *= gm;
                }
                *(float2*)(out + (size_t)row * NA + cb) = make_float2(v0, v1);
            }
        }
    }
}

// ---------------- chunked linear scan (1 channel/thread, 256-thread blocks) ----------------
__global__ __launch_bounds__(256)
void pass_scan_local(const float* __restrict__ time_w,
                     const float* __restrict__ time_alpha)
{
    const int n = blockIdx.x * 256 + threadIdx.x;
    const int j = blockIdx.y;
    const int b = blockIdx.z;
    const int h = n >> 4;
    const float wlast = time_w[h * CTX + CTX - 1];
    const float ratio = time_w[h * CTX + CTX - 2] / wlast;
    float S = 0.f, ks = 0.f;
    const size_t base = ((size_t)(b * TT + j * CL)) * NA + n;
    const float* al = time_alpha + h * CTX + j * CL;
#pragma unroll 8
    for (int u = 0; u < CL; u++) {
        const float kk = g_k[base + (size_t)u * NA];
        const float vv = g_v[base + (size_t)u * NA];
        S  = fmaf(S, ratio, wlast * al[u] * kk * vv);
        ks += kk;
    }
    const int o = (b * NC + j) * NA + n;
    g_Send[o] = S;
    g_Ksum[o] = ks;
}

// final: fused cross-chunk carry (prefix over Send/Ksum) + chunk replay.
// rwkv = sigmoid(r)*beta*S/ks, written as tf32 fragment-packed A tiles (into g_Atf)
__global__ __launch_bounds__(256)
void pass_scan_final(const float* __restrict__ time_w,
                     const float* __restrict__ time_alpha,
                     const float* __restrict__ time_beta)
{
    const int n = blockIdx.x * 256 + threadIdx.x;
    const int j = blockIdx.y;
    const int b = blockIdx.z;
    const int h = n >> 4;
    const float wlast = time_w[h * CTX + CTX - 1];
    const float ratio = time_w[h * CTX + CTX - 2] / wlast;

    // carry-in: prefix of chunk end-states 0..j-1 (independent loads, short FMA chain)
    float rL = ratio;
#pragma unroll
    for (int i = 0; i < 5; i++) rL *= rL;    // ratio^32 (CL=32)
    float S = 0.f, ks = 0.f;
    {
        const float* ps = g_Send + (size_t)(b * NC) * NA + n;
        const float* pk = g_Ksum + (size_t)(b * NC) * NA + n;
#pragma unroll 8
        for (int i = 0; i < j; i++) {
            S  = S * rL + ps[(size_t)i * NA];
            ks += pk[(size_t)i * NA];
        }
    }

    const size_t base = ((size_t)(b * TT + j * CL)) * NA + n;
    const float* al = time_alpha + h * CTX + j * CL;
    const float* be = time_beta  + h * CTX + j * CL;
    // channel-derived invariants of the fragment address
    const int s_n   = (n & 63) >> 3;
    const int n3    = n & 3;
    const int slotn = ((n & 7) >= 4) ? 2 : 0;
    const int tkcol = n >> 6;
#pragma unroll 8
    for (int u = 0; u < CL; u++) {
        const size_t off = base + (size_t)u * NA;
        const float kk = g_k[off];
        const float vv = g_v[off];
        const float sr = g_r[off];
        S  = fmaf(S, ratio, wlast * al[u] * kk * vv);
        ks += kk;
        const float val = sr * be[u] * __fdividef(S, ks);
        const int tg    = j * CL + u;
        const int tile  = (b * 8 + (tg >> 7)) * 16 + tkcol;
        const int mf    = (tg & 127) >> 4;
        const int rowin = tg & 15;
        const int slot  = (rowin >> 3) + slotn;
        const int lfrag = (rowin & 7) * 4 + n3;
        const int g     = s_n * 8 + mf;
        g_Atf[(size_t)tile * ATILE_F + (size_t)(g * 32 + lfrag) * 4 + slot]
            = __uint_as_float(tf32r(val));
    }
}

// ---------------- launch ----------------
extern "C" void kernel_launch(void* const* d_in, const int* in_sizes, int n_in,
                              void* d_out, int out_size)
{
    const float* x          = (const float*)d_in[0];
    const float* time_w     = (const float*)d_in[1];
    const float* time_alpha = (const float*)d_in[2];
    const float* time_beta  = (const float*)d_in[3];
    const float* time_gamma = (const float*)d_in[4];
    const float* Wk = (const float*)d_in[5];
    const float* bk = (const float*)d_in[6];
    const float* Wv = (const float*)d_in[7];
    const float* bv = (const float*)d_in[8];
    const float* Wr = (const float*)d_in[9];
    const float* br = (const float*)d_in[10];
    const float* Wo = (const float*)d_in[11];
    const float* bo = (const float*)d_in[12];
    float* out = (float*)d_out;

    cudaFuncSetAttribute(gemm_tf, cudaFuncAttributeMaxDynamicSharedMemorySize, SMEMT);

    // merged operand conversions (A path + B path in one launch)
    conv_all<<<8192, 256>>>(x, Wk, Wv, Wr, Wo);

    // fused K/V/R projections (tf32, CTA 256x128)
    gemm_tf<<<dim3(24, 16), 256, SMEMT>>>(-1, bk, bv, br, bo, time_gamma, out);

    // chunked linear recurrence; final fuses the cross-chunk carry and writes
    // rwkv into g_Atf (tf32 fragment layout)
    pass_scan_local <<<dim3(4, NC, BB), 256>>>(time_w, time_alpha);
    pass_scan_final <<<dim3(4, NC, BB), 256>>>(time_w, time_alpha, time_beta);

    // output projection (tf32) with gamma epilogue
    gemm_tf<<<dim3(8, 16), 256, SMEMT>>>(3, bk, bv, br, bo, time_gamma, out);
}

// round 10
// speedup vs baseline: 1.4417x; 1.4417x over previous
#include <cuda_runtime.h>
#include <cuda_bf16.h>
#include <math.h>
#include <stdint.h>

// ---------------- problem constants ----------------
#define BB   4
#define TT   1024
#define HID  1024
#define NA   1024
#define CTX  1024
#define NC   32
#define CL   32

// ---------------- GEMM tiling ----------------
// CTA tile 256(M) x 128(N), K-chunk 64, 8 warps, warp tile 64x64.
#define ATILE_F 8192        // one 128x64 tf32 tile = 8192 floats = 32KB
#define STG     98304       // stage: 2 A tiles + 1 B tile = 96KB
#define SMEMT   (1024 + 2*STG)

// ---------------- static scratch ----------------
__device__ float g_k[BB*TT*NA];
__device__ float g_v[BB*TT*NA];
__device__ float g_r[BB*TT*NA];
__device__ float g_Send[BB*NC*NA];
__device__ float g_Ksum[BB*NC*NA];
__device__ float g_cS[BB*NC*NA];
__device__ float g_cK[BB*NC*NA];
// tf32 fragment-packed operands (A reused: xs for KVR, then rwkv for Wo)
__device__ __align__(16) float g_Atf[BB*TT*HID];   // 512 tiles of 128x64
__device__ __align__(16) float g_Wtf[4*HID*NA];    // 4 weights x 128 tiles

// ---------------- ptx helpers (baseline features only) ----------------
__device__ __forceinline__ uint32_t smem_u32(const void* p) {
    uint32_t a;
    asm("{ .reg .u64 t; cvta.to.shared.u64 t, %1; cvt.u32.u64 %0, t; }" : "=r"(a) : "l"(p));
    return a;
}
#define MBAR_INIT(a, c) \
    asm volatile("mbarrier.init.shared.b64 [%0], %1;" :: "r"(a), "r"(c) : "memory")
#define MBAR_EXPECT_TX(a, b) \
    asm volatile("mbarrier.arrive.expect_tx.shared.b64 _, [%0], %1;" :: "r"(a), "r"(b) : "memory")
#define MBAR_ARRIVE(a) \
    asm volatile("mbarrier.arrive.shared.b64 _, [%0];" :: "r"(a) : "memory")
#define MBAR_WAIT(a, ph) do { \
    asm volatile("{\n\t.reg .pred P;\n\tWL%=:\n\t" \
        "mbarrier.try_wait.parity.acquire.cta.shared::cta.b64 P, [%0], %1, 0x989680;\n\t" \
        "@P bra.uni WD%=;\n\tbra.uni WL%=;\n\tWD%=:\n\t}" \
        :: "r"(a), "r"(ph) : "memory"); } while (0)

__device__ __forceinline__ void bulk_ldg(uint32_t dst, const void* src, uint32_t bytes, uint32_t mbar) {
    asm volatile("cp.async.bulk.shared::cluster.global.mbarrier::complete_tx::bytes [%0], [%1], %2, [%3];"
        :: "r"(dst), "l"((unsigned long long)__cvta_generic_to_global(src)), "r"(bytes), "r"(mbar) : "memory");
}
__device__ __forceinline__ void mma1688tf(float* d, const uint32_t* a, const uint32_t* b) {
    asm volatile("mma.sync.aligned.m16n8k8.row.col.f32.tf32.tf32.f32 "
        "{%0,%1,%2,%3}, {%4,%5,%6,%7}, {%8,%9}, {%0,%1,%2,%3};"
        : "+f"(d[0]), "+f"(d[1]), "+f"(d[2]), "+f"(d[3])
        : "r"(a[0]), "r"(a[1]), "r"(a[2]), "r"(a[3]), "r"(b[0]), "r"(b[1]));
}
__device__ __forceinline__ uint32_t tf32r(float v) {
    uint32_t r;
    asm("cvt.rna.tf32.f32 %0, %1;" : "=r"(r) : "f"(v));
    return r;
}
// x with RWKV time shift
__device__ __forceinline__ float ldx(const float* __restrict__ x, int m, int k) {
    const int t = m & (TT - 1);
    if (k < HID / 2) return (t > 0) ? x[(size_t)(m - 1) * HID + k] : 0.f;
    return x[(size_t)m * HID + k];
}

// ---------------- merged conversion: xs -> A tiles, W* -> B tiles ----------------
// blockIdx.x < 4096: A path.  >= 4096: B path.
// A frag map (m16n8k8.tf32): a0=(m0,k0), a1=(m0+8,k0), a2=(m0,k0+4), a3=(m0+8,k0+4)
// B pair-packed: cell (gp=s*8+fp, l) = {b0(f=2fp), b1(f=2fp), b0(f=2fp+1), b1(f=2fp+1)}
__global__ __launch_bounds__(256)
void conv_all(const float* __restrict__ x,
              const float* __restrict__ Wk, const float* __restrict__ Wv,
              const float* __restrict__ Wr, const float* __restrict__ Wo)
{
    if (blockIdx.x < 4096) {
        const int idx = blockIdx.x * 256 + threadIdx.x;
        const int l = idx & 31;
        const int g = (idx >> 5) & 63;       // g = s*8 + mf
        const int tile = idx >> 11;          // tile = tm128*16 + tk
        const int tm = tile >> 4, tk = tile & 15;
        const int s = g >> 3, mf = g & 7;
        const int m0 = tm * 128 + mf * 16 + (l >> 2);
        const int k0 = tk * 64 + s * 8 + (l & 3);
        uint4 q;
        q.x = tf32r(ldx(x, m0,     k0));
        q.y = tf32r(ldx(x, m0 + 8, k0));
        q.z = tf32r(ldx(x, m0,     k0 + 4));
        q.w = tf32r(ldx(x, m0 + 8, k0 + 4));
        *(uint4*)(g_Atf + (size_t)tile * ATILE_F + (size_t)(g * 32 + l) * 4) = q;
    } else {
        const int idx = (blockIdx.x - 4096) * 256 + threadIdx.x;
        const int l = idx & 31;
        const int gp = (idx >> 5) & 63;      // gp = s*8 + fp
        const int tile = idx >> 11;          // tile = widx*128 + tn*16 + tk
        const int widx = tile >> 7;
        const int rem = tile & 127;
        const int tn = rem >> 4, tk = rem & 15;
        const int s = gp >> 3, fp = gp & 7;
        const int k0 = tk * 64 + s * 8 + (l & 3);
        const int ne = tn * 128 + fp * 16 + (l >> 2);
        const float* W = (widx == 0) ? Wk : (widx == 1) ? Wv : (widx == 2) ? Wr : Wo;
        uint4 q;
        q.x = tf32r(W[(size_t)k0 * NA + ne]);
        q.y = tf32r(W[(size_t)(k0 + 4) * NA + ne]);
        q.z = tf32r(W[(size_t)k0 * NA + ne + 8]);
        q.w = tf32r(W[(size_t)(k0 + 4) * NA + ne + 8]);
        *(uint4*)(g_Wtf + (size_t)tile * ATILE_F + (size_t)(gp * 32 + l) * 4) = q;
    }
}

// ---------------- tf32 GEMM: C[4096, 1024-slice] = A @ W (+bias, +act) ----------------
// CTA 256x128, warp tile 64x64.  widx: 0=K(exp-clip) 1=V 2=R(sigmoid) 3=Wo(*gamma, ->obuf)
__global__ __launch_bounds__(256, 1)
void gemm_tf(int widx_fixed,
             const float* __restrict__ bk, const float* __restrict__ bv,
             const float* __restrict__ br, const float* __restrict__ bo,
             const float* __restrict__ gamma, float* __restrict__ obuf)
{
    extern __shared__ char smem_raw[];
    char* smem_al = (char*)(((uintptr_t)smem_raw + 1023) & ~(uintptr_t)1023);
    const uint32_t sb = smem_u32(smem_al);
    const int tid = threadIdx.x, l = tid & 31, w = tid >> 5;
    const int wm = w & 3, wn = w >> 2;        // 4 M-warps x 2 N-warps
    int widx, tn;
    if (widx_fixed >= 0) { widx = widx_fixed; tn = blockIdx.x; }
    else                 { widx = blockIdx.x >> 3; tn = blockIdx.x & 7; }
    const int tm = blockIdx.y;                // 16 tiles of 256 rows

    if (tid == 0) {
        MBAR_INIT(sb + 0, 1);
        MBAR_INIT(sb + 8, 1);
        MBAR_INIT(sb + 64, 256);
        MBAR_INIT(sb + 72, 256);
    }
    __syncthreads();

    const float* A0 = g_Atf + ((size_t)(tm * 2)     * 16) * ATILE_F;
    const float* A1 = g_Atf + ((size_t)(tm * 2 + 1) * 16) * ATILE_F;
    const float* Bw = g_Wtf + ((size_t)(widx * 8 + tn) * 16) * ATILE_F;

    if (tid == 0) {
#pragma unroll
        for (int c = 0; c < 2; c++) {
            const uint32_t st = sb + 1024 + c * STG;
            MBAR_EXPECT_TX(sb + 8 * c, STG);
            bulk_ldg(st,         A0 + (size_t)c * ATILE_F, 32768, sb + 8 * c);
            bulk_ldg(st + 32768, A1 + (size_t)c * ATILE_F, 32768, sb + 8 * c);
            bulk_ldg(st + 65536, Bw + (size_t)c * ATILE_F, 32768, sb + 8 * c);
        }
    }

    float acc[4][8][4];
#pragma unroll
    for (int i = 0; i < 4; i++)
#pragma unroll
        for (int j = 0; j < 8; j++)
#pragma unroll
            for (int q = 0; q < 4; q++) acc[i][j][q] = 0.f;

    const uint32_t a_wbase = (uint32_t)(wm >> 1) * 32768 + ((uint32_t)(wm & 1) * 4 * 32 + l) * 16;
    const uint32_t b_wbase = 65536u + ((uint32_t)wn * 4 * 32 + l) * 16;

    for (int c = 0; c < 16; c++) {
        const int s = c & 1;
        const uint32_t par = (uint32_t)((c >> 1) & 1);
        MBAR_WAIT(sb + 8 * s, par);
        const char* stp = smem_al + 1024 + s * STG;
        const char* ap = stp + a_wbase;
        const char* bp = stp + b_wbase;
#pragma unroll 2
        for (int ks = 0; ks < 8; ks++) {
            uint4 Aq[4], Bq[4];
#pragma unroll
            for (int mt = 0; mt < 4; mt++)
                Aq[mt] = *(const uint4*)(ap + (uint32_t)(ks * 8 + mt) * 512);
#pragma unroll
            for (int ntp = 0; ntp < 4; ntp++)
                Bq[ntp] = *(const uint4*)(bp + (uint32_t)(ks * 8 + ntp) * 512);
#pragma unroll
            for (int mt = 0; mt < 4; mt++) {
                const uint32_t Af[4] = {Aq[mt].x, Aq[mt].y, Aq[mt].z, Aq[mt].w};
#pragma unroll
                for (int ntp = 0; ntp < 4; ntp++) {
                    const uint32_t B0[2] = {Bq[ntp].x, Bq[ntp].y};
                    const uint32_t B1[2] = {Bq[ntp].z, Bq[ntp].w};
                    mma1688tf(acc[mt][2 * ntp],     Af, B0);
                    mma1688tf(acc[mt][2 * ntp + 1], Af, B1);
                }
            }
        }
        MBAR_ARRIVE(sb + 64 + 8 * s);
        if (tid == 0 && c + 2 < 16) {
            MBAR_WAIT(sb + 64 + 8 * s, par);
            const int cc = c + 2;
            const uint32_t st = sb + 1024 + s * STG;
            MBAR_EXPECT_TX(sb + 8 * s, STG);
            bulk_ldg(st,         A0 + (size_t)cc * ATILE_F, 32768, sb + 8 * s);
            bulk_ldg(st + 32768, A1 + (size_t)cc * ATILE_F, 32768, sb + 8 * s);
            bulk_ldg(st + 65536, Bw + (size_t)cc * ATILE_F, 32768, sb + 8 * s);
        }
    }

    // ---- epilogue ----
    const float* bias = (widx == 0) ? bk : (widx == 1) ? bv : (widx == 2) ? br : bo;
    float* out = (widx == 0) ? g_k : (widx == 1) ? g_v : (widx == 2) ? g_r : obuf;
    const int mrow_base = tm * 256 + wm * 64;
    const int col_base  = tn * 128 + wn * 64;
#pragma unroll
    for (int mt = 0; mt < 4; mt++) {
#pragma unroll
        for (int nt = 0; nt < 8; nt++) {
            const int r0 = mrow_base + mt * 16 + (l >> 2);
            const int cb = col_base + nt * 8 + (l & 3) * 2;
            const float b0 = bias[cb], b1 = bias[cb + 1];
#pragma unroll
            for (int half = 0; half < 2; half++) {
                const int row = r0 + half * 8;
                float v0 = acc[mt][nt][half * 2]     + b0;
                float v1 = acc[mt][nt][half * 2 + 1] + b1;
                if (widx == 0) {
                    v0 = __expf(fminf(fmaxf(v0, -60.f), 30.f));
                    v1 = __expf(fminf(fmaxf(v1, -60.f), 30.f));
                } else if (widx == 2) {
                    v0 = __fdividef(1.f, 1.f + __expf(-v0));
                    v1 = __fdividef(1.f, 1.f + __expf(-v1));
                } else if (widx == 3) {
                    const float gm = gamma[row & (TT - 1)];
                    v0 *= gm; v1 *= gm;
                }
                *(float2*)(out + (size_t)row * NA + cb) = make_float2(v0, v1);
            }
        }
    }
}

// ---------------- chunked linear scan (1 channel/thread, 256-thread blocks) ----------------
__global__ __launch_bounds__(256)
void pass_scan_local(const float* __restrict__ time_w,
                     const float* __restrict__ time_alpha)
{
    const int n = blockIdx.x * 256 + threadIdx.x;
    const int j = blockIdx.y;
    const int b = blockIdx.z;
    const int h = n >> 4;
    const float wlast = time_w[h * CTX + CTX - 1];
    const float ratio = time_w[h * CTX + CTX - 2] / wlast;
    float S = 0.f, ks = 0.f;
    const size_t base = ((size_t)(b * TT + j * CL)) * NA + n;
    const float* al = time_alpha + h * CTX + j * CL;
#pragma unroll 8
    for (int u = 0; u < CL; u++) {
        const float kk = g_k[base + (size_t)u * NA];
        const float vv = g_v[base + (size_t)u * NA];
        S  = fmaf(S, ratio, wlast * al[u] * kk * vv);
        ks += kk;
    }
    const int o = (b * NC + j) * NA + n;
    g_Send[o] = S;
    g_Ksum[o] = ks;
}

// carry: batched-load exclusive scan across the NC chunk end-states.
// All 2*NC loads are independent (issued up-front, MLP~64), then a register
// FMA chain, then 2*NC stores — one memory latency instead of NC round-trips.
__global__ __launch_bounds__(128)
void pass_scan_carry(const float* __restrict__ time_w)
{
    const int idx = blockIdx.x * 128 + threadIdx.x;   // BB*NA threads
    const int n = idx & (NA - 1);
    const int b = idx >> 10;
    const int h = n >> 4;
    const float ratio = time_w[h * CTX + CTX - 2] / time_w[h * CTX + CTX - 1];
    float rL = ratio;
#pragma unroll
    for (int i = 0; i < 5; i++) rL *= rL;   // ratio^32 (CL=32)

    const float* ps = g_Send + (size_t)(b * NC) * NA + n;
    const float* pk = g_Ksum + (size_t)(b * NC) * NA + n;
    float se[NC], ku[NC];
#pragma unroll
    for (int j = 0; j < NC; j++) {          // independent loads, batched
        se[j] = ps[(size_t)j * NA];
        ku[j] = pk[(size_t)j * NA];
    }
    float cS = 0.f, cK = 0.f;
#pragma unroll
    for (int j = 0; j < NC; j++) {          // register scan
        const float ns = cS * rL + se[j];
        const float nk = cK + ku[j];
        se[j] = cS; ku[j] = cK;             // exclusive prefix in-place
        cS = ns; cK = nk;
    }
    float* qs = g_cS + (size_t)(b * NC) * NA + n;
    float* qk = g_cK + (size_t)(b * NC) * NA + n;
#pragma unroll
    for (int j = 0; j < NC; j++) {
        qs[(size_t)j * NA] = se[j];
        qk[(size_t)j * NA] = ku[j];
    }
}

// final: rwkv = sigmoid(r)*beta*S/ks, written as tf32 fragment-packed A tiles (into g_Atf)
__global__ __launch_bounds__(256)
void pass_scan_final(const float* __restrict__ time_w,
                     const float* __restrict__ time_alpha,
                     const float* __restrict__ time_beta)
{
    const int n = blockIdx.x * 256 + threadIdx.x;
    const int j = blockIdx.y;
    const int b = blockIdx.z;
    const int h = n >> 4;
    const float wlast = time_w[h * CTX + CTX - 1];
    const float ratio = time_w[h * CTX + CTX - 2] / wlast;
    const int o = (b * NC + j) * NA + n;
    float S  = g_cS[o];
    float ks = g_cK[o];
    const size_t base = ((size_t)(b * TT + j * CL)) * NA + n;
    const float* al = time_alpha + h * CTX + j * CL;
    const float* be = time_beta  + h * CTX + j * CL;
    // channel-derived invariants of the fragment address
    const int s_n   = (n & 63) >> 3;
    const int n3    = n & 3;
    const int slotn = ((n & 7) >= 4) ? 2 : 0;
    const int tkcol = n >> 6;
#pragma unroll 8
    for (int u = 0; u < CL; u++) {
        const size_t off = base + (size_t)u * NA;
        const float kk = g_k[off];
        const float vv = g_v[off];
        const float sr = g_r[off];
        S  = fmaf(S, ratio, wlast * al[u] * kk * vv);
        ks += kk;
        const float val = sr * be[u] * __fdividef(S, ks);
        const int tg    = j * CL + u;
        const int tile  = (b * 8 + (tg >> 7)) * 16 + tkcol;
        const int mf    = (tg & 127) >> 4;
        const int rowin = tg & 15;
        const int slot  = (rowin >> 3) + slotn;
        const int lfrag = (rowin & 7) * 4 + n3;
        const int g     = s_n * 8 + mf;
        g_Atf[(size_t)tile * ATILE_F + (size_t)(g * 32 + lfrag) * 4 + slot]
            = __uint_as_float(tf32r(val));
    }
}

// ---------------- launch ----------------
extern "C" void kernel_launch(void* const* d_in, const int* in_sizes, int n_in,
                              void* d_out, int out_size)
{
    const float* x          = (const float*)d_in[0];
    const float* time_w     = (const float*)d_in[1];
    const float* time_alpha = (const float*)d_in[2];
    const float* time_beta  = (const float*)d_in[3];
    const float* time_gamma = (const float*)d_in[4];
    const float* Wk = (const float*)d_in[5];
    const float* bk = (const float*)d_in[6];
    const float* Wv = (const float*)d_in[7];
    const float* bv = (const float*)d_in[8];
    const float* Wr = (const float*)d_in[9];
    const float* br = (const float*)d_in[10];
    const float* Wo = (const float*)d_in[11];
    const float* bo = (const float*)d_in[12];
    float* out = (float*)d_out;

    cudaFuncSetAttribute(gemm_tf, cudaFuncAttributeMaxDynamicSharedMemorySize, SMEMT);

    // merged operand conversions (A path + B path in one launch)
    conv_all<<<8192, 256>>>(x, Wk, Wv, Wr, Wo);

    // fused K/V/R projections (tf32, CTA 256x128)
    gemm_tf<<<dim3(24, 16), 256, SMEMT>>>(-1, bk, bv, br, bo, time_gamma, out);

    // chunked linear recurrence; writes rwkv into g_Atf (tf32 fragment layout)
    pass_scan_local <<<dim3(4, NC, BB), 256>>>(time_w, time_alpha);
    pass_scan_carry <<<(BB * NA) / 128, 128>>>(time_w);
    pass_scan_final <<<dim3(4, NC, BB), 256>>>(time_w, time_alpha, time_beta);

    // output projection (tf32) with gamma epilogue
    gemm_tf<<<dim3(8, 16), 256, SMEMT>>>(3, bk, bv, br, bo, time_gamma, out);
}

// round 11
// speedup vs baseline: 2.3538x; 1.6326x over previous
#include <cuda_runtime.h>
#include <cuda_fp16.h>
#include <math.h>
#include <stdint.h>

// ---------------- problem constants ----------------
#define BB   4
#define TT   1024
#define HID  1024
#define NA   1024
#define CTX  1024
#define NC   32
#define CL   32

// ---------------- GEMM tiling ----------------
// CTA tile 256(M) x 128(N), K-chunk 64, 8 warps, warp tile 64x64, fp16 operands.
#define ATILE_H   8192      // one 128x64 fp16 tile = 8192 halfs = 16KB
#define ATILE_B   16384
#define STG       49152     // stage: 2 A tiles + 1 B tile = 48KB
#define NSTAGE    3
#define SMEMT     (1024 + NSTAGE*STG)

// ---------------- static scratch ----------------
__device__ float g_k[BB*TT*NA];
__device__ float g_v[BB*TT*NA];
__device__ float g_r[BB*TT*NA];
__device__ float g_Send[BB*NC*NA];
__device__ float g_Ksum[BB*NC*NA];
__device__ float g_cS[BB*NC*NA];
__device__ float g_cK[BB*NC*NA];
// fp16 fragment-packed operands (A reused: xs for KVR, then rwkv for Wo)
__device__ __align__(16) __half g_Ah[BB*TT*HID];   // 512 tiles of 128x64
__device__ __align__(16) __half g_Wh[4*HID*NA];    // 4 weights x 128 tiles

// ---------------- ptx helpers (baseline features only) ----------------
__device__ __forceinline__ uint32_t smem_u32(const void* p) {
    uint32_t a;
    asm("{ .reg .u64 t; cvta.to.shared.u64 t, %1; cvt.u32.u64 %0, t; }" : "=r"(a) : "l"(p));
    return a;
}
#define MBAR_INIT(a, c) \
    asm volatile("mbarrier.init.shared.b64 [%0], %1;" :: "r"(a), "r"(c) : "memory")
#define MBAR_EXPECT_TX(a, b) \
    asm volatile("mbarrier.arrive.expect_tx.shared.b64 _, [%0], %1;" :: "r"(a), "r"(b) : "memory")
#define MBAR_ARRIVE(a) \
    asm volatile("mbarrier.arrive.shared.b64 _, [%0];" :: "r"(a) : "memory")
#define MBAR_WAIT(a, ph) do { \
    asm volatile("{\n\t.reg .pred P;\n\tWL%=:\n\t" \
        "mbarrier.try_wait.parity.acquire.cta.shared::cta.b64 P, [%0], %1, 0x989680;\n\t" \
        "@P bra.uni WD%=;\n\tbra.uni WL%=;\n\tWD%=:\n\t}" \
        :: "r"(a), "r"(ph) : "memory"); } while (0)

__device__ __forceinline__ void bulk_ldg(uint32_t dst, const void* src, uint32_t bytes, uint32_t mbar) {
    asm volatile("cp.async.bulk.shared::cluster.global.mbarrier::complete_tx::bytes [%0], [%1], %2, [%3];"
        :: "r"(dst), "l"((unsigned long long)__cvta_generic_to_global(src)), "r"(bytes), "r"(mbar) : "memory");
}
__device__ __forceinline__ void mma16816h(float* d, const uint32_t* a, const uint32_t* b) {
    asm volatile("mma.sync.aligned.m16n8k16.row.col.f32.f16.f16.f32 "
        "{%0,%1,%2,%3}, {%4,%5,%6,%7}, {%8,%9}, {%0,%1,%2,%3};"
        : "+f"(d[0]), "+f"(d[1]), "+f"(d[2]), "+f"(d[3])
        : "r"(a[0]), "r"(a[1]), "r"(a[2]), "r"(a[3]), "r"(b[0]), "r"(b[1]));
}
__device__ __forceinline__ uint32_t h2(float a, float b) {
    __half2 t = __floats2half2_rn(a, b);
    return *(uint32_t*)&t;
}
// x with RWKV time shift, float2 (k always even, never crossing the 512 split)
__device__ __forceinline__ float2 ldx2(const float* __restrict__ x, int m, int k) {
    const int t = m & (TT - 1);
    if (k < HID / 2) {
        if (t > 0) return *(const float2*)(x + (size_t)(m - 1) * HID + k);
        return make_float2(0.f, 0.f);
    }
    return *(const float2*)(x + (size_t)m * HID + k);
}

// ---------------- merged conversion: xs -> A tiles, W* -> B tiles (fp16 frags) ----------------
// A frag map (m16n8k16.f16): a0=(m0,k0 pair), a1=(m0+8,k0 pair), a2=(m0,k0+8 pair), a3=(m0+8,k0+8 pair)
// Tile = 128Mx64K: cell(g = s*8+mf, l) = 16B {a0,a1,a2,a3}; s = k16 group, mf = m16 frag.
// B pair-packed: cell(gp = s*8+fp, l) = {b0(nt=2fp), b1(nt=2fp), b0(nt=2fp+1), b1(nt=2fp+1)}
__global__ __launch_bounds__(256)
void conv_all(const float* __restrict__ x,
              const float* __restrict__ Wk, const float* __restrict__ Wv,
              const float* __restrict__ Wr, const float* __restrict__ Wo)
{
    if (blockIdx.x < 2048) {
        const int idx = blockIdx.x * 256 + threadIdx.x;   // 512 tiles * 32 g * 32 l
        const int l = idx & 31;
        const int g = (idx >> 5) & 31;       // g = s*8 + mf
        const int tile = idx >> 10;          // tile = tm128*16 + tk
        const int tm = tile >> 4, tk = tile & 15;
        const int s = g >> 3, mf = g & 7;
        const int m0 = tm * 128 + mf * 16 + (l >> 2);
        const int k0 = tk * 64 + s * 16 + (l & 3) * 2;
        const float2 v00 = ldx2(x, m0,     k0);
        const float2 v10 = ldx2(x, m0 + 8, k0);
        const float2 v01 = ldx2(x, m0,     k0 + 8);
        const float2 v11 = ldx2(x, m0 + 8, k0 + 8);
        uint4 q;
        q.x = h2(v00.x, v00.y);
        q.y = h2(v10.x, v10.y);
        q.z = h2(v01.x, v01.y);
        q.w = h2(v11.x, v11.y);
        *(uint4*)((char*)g_Ah + (size_t)tile * ATILE_B + (size_t)(g * 32 + l) * 16) = q;
    } else {
        const int idx = (blockIdx.x - 2048) * 256 + threadIdx.x;  // 512 tiles * 32 gp * 32 l
        const int l = idx & 31;
        const int gp = (idx >> 5) & 31;      // gp = s*8 + fp
        const int tile = idx >> 10;          // tile = widx*128 + tn*16 + tk
        const int widx = tile >> 7;
        const int rem = tile & 127;
        const int tn = rem >> 4, tk = rem & 15;
        const int s = gp >> 3, fp = gp & 7;
        const int k0 = tk * 64 + s * 16 + (l & 3) * 2;
        const int ne = tn * 128 + fp * 16 + (l >> 2);
        const float* W = (widx == 0) ? Wk : (widx == 1) ? Wv : (widx == 2) ? Wr : Wo;
        uint4 q;
        q.x = h2(W[(size_t)k0 * NA + ne],         W[(size_t)(k0 + 1) * NA + ne]);
        q.y = h2(W[(size_t)(k0 + 8) * NA + ne],   W[(size_t)(k0 + 9) * NA + ne]);
        q.z = h2(W[(size_t)k0 * NA + ne + 8],     W[(size_t)(k0 + 1) * NA + ne + 8]);
        q.w = h2(W[(size_t)(k0 + 8) * NA + ne + 8], W[(size_t)(k0 + 9) * NA + ne + 8]);
        *(uint4*)((char*)g_Wh + (size_t)tile * ATILE_B + (size_t)(gp * 32 + l) * 16) = q;
    }
}

// ---------------- fp16 GEMM: C[4096, 1024-slice] = A @ W (+bias, +act) ----------------
// CTA 256x128, warp tile 64x64.  widx: 0=K(exp-clip) 1=V 2=R(sigmoid) 3=Wo(*gamma, ->obuf)
__global__ __launch_bounds__(256, 1)
void gemm_h(int widx_fixed,
            const float* __restrict__ bk, const float* __restrict__ bv,
            const float* __restrict__ br, const float* __restrict__ bo,
            const float* __restrict__ gamma, float* __restrict__ obuf)
{
    extern __shared__ char smem_raw[];
    char* smem_al = (char*)(((uintptr_t)smem_raw + 1023) & ~(uintptr_t)1023);
    const uint32_t sb = smem_u32(smem_al);
    const int tid = threadIdx.x, l = tid & 31, w = tid >> 5;
    const int wm = w & 3, wn = w >> 2;        // 4 M-warps x 2 N-warps
    int widx, tn;
    if (widx_fixed >= 0) { widx = widx_fixed; tn = blockIdx.x; }
    else                 { widx = blockIdx.x >> 3; tn = blockIdx.x & 7; }
    const int tm = blockIdx.y;                // 16 tiles of 256 rows

    if (tid == 0) {
#pragma unroll
        for (int s = 0; s < NSTAGE; s++) {
            MBAR_INIT(sb + 8 * s, 1);
            MBAR_INIT(sb + 64 + 8 * s, 256);
        }
    }
    __syncthreads();

    const __half* A0 = g_Ah + ((size_t)(tm * 2)     * 16) * ATILE_H;
    const __half* A1 = g_Ah + ((size_t)(tm * 2 + 1) * 16) * ATILE_H;
    const __half* Bw = g_Wh + ((size_t)(widx * 8 + tn) * 16) * ATILE_H;

    if (tid == 0) {
#pragma unroll
        for (int c = 0; c < NSTAGE; c++) {
            const uint32_t st = sb + 1024 + c * STG;
            MBAR_EXPECT_TX(sb + 8 * c, STG);
            bulk_ldg(st,         A0 + (size_t)c * ATILE_H, ATILE_B, sb + 8 * c);
            bulk_ldg(st + 16384, A1 + (size_t)c * ATILE_H, ATILE_B, sb + 8 * c);
            bulk_ldg(st + 32768, Bw + (size_t)c * ATILE_H, ATILE_B, sb + 8 * c);
        }
    }

    float acc[4][8][4];
#pragma unroll
    for (int i = 0; i < 4; i++)
#pragma unroll
        for (int j = 0; j < 8; j++)
#pragma unroll
            for (int q = 0; q < 4; q++) acc[i][j][q] = 0.f;

    // A: warp wm reads half-tile (wm>>1); m16 frags mf = (wm&1)*4 + mt
    const uint32_t a_wbase = (uint32_t)(wm >> 1) * 16384 + ((uint32_t)((wm & 1) * 4) * 32 + l) * 16;
    // B: gp = s*8 + wn*4 + ntp
    const uint32_t b_wbase = 32768u + ((uint32_t)(wn * 4) * 32 + l) * 16;

    for (int c = 0; c < 16; c++) {
        const int s = c % NSTAGE;
        const uint32_t par = (uint32_t)((c / NSTAGE) & 1);
        MBAR_WAIT(sb + 8 * s, par);
        const char* stp = smem_al + 1024 + s * STG;
        const char* ap = stp + a_wbase;
        const char* bp = stp + b_wbase;
#pragma unroll 2
        for (int ks = 0; ks < 4; ks++) {      // k16 steps within the 64-chunk
            uint4 Aq[4], Bq[4];
#pragma unroll
            for (int mt = 0; mt < 4; mt++)
                Aq[mt] = *(const uint4*)(ap + (uint32_t)(ks * 8 + mt) * 512);
#pragma unroll
            for (int ntp = 0; ntp < 4; ntp++)
                Bq[ntp] = *(const uint4*)(bp + (uint32_t)(ks * 8 + ntp) * 512);
#pragma unroll
            for (int mt = 0; mt < 4; mt++) {
                const uint32_t Af[4] = {Aq[mt].x, Aq[mt].y, Aq[mt].z, Aq[mt].w};
#pragma unroll
                for (int ntp = 0; ntp < 4; ntp++) {
                    const uint32_t B0[2] = {Bq[ntp].x, Bq[ntp].y};
                    const uint32_t B1[2] = {Bq[ntp].z, Bq[ntp].w};
                    mma16816h(acc[mt][2 * ntp],     Af, B0);
                    mma16816h(acc[mt][2 * ntp + 1], Af, B1);
                }
            }
        }
        MBAR_ARRIVE(sb + 64 + 8 * s);
        if (tid == 0 && c + NSTAGE < 16) {
            MBAR_WAIT(sb + 64 + 8 * s, par);
            const int cc = c + NSTAGE;
            const uint32_t st = sb + 1024 + s * STG;
            MBAR_EXPECT_TX(sb + 8 * s, STG);
            bulk_ldg(st,         A0 + (size_t)cc * ATILE_H, ATILE_B, sb + 8 * s);
            bulk_ldg(st + 16384, A1 + (size_t)cc * ATILE_H, ATILE_B, sb + 8 * s);
            bulk_ldg(st + 32768, Bw + (size_t)cc * ATILE_H, ATILE_B, sb + 8 * s);
        }
    }

    // ---- epilogue ----
    const float* bias = (widx == 0) ? bk : (widx == 1) ? bv : (widx == 2) ? br : bo;
    float* out = (widx == 0) ? g_k : (widx == 1) ? g_v : (widx == 2) ? g_r : obuf;
    const int mrow_base = tm * 256 + wm * 64;
    const int col_base  = tn * 128 + wn * 64;
#pragma unroll
    for (int mt = 0; mt < 4; mt++) {
#pragma unroll
        for (int nt = 0; nt < 8; nt++) {
            const int r0 = mrow_base + mt * 16 + (l >> 2);
            const int cb = col_base + nt * 8 + (l & 3) * 2;
            const float b0 = bias[cb], b1 = bias[cb + 1];
#pragma unroll
            for (int half = 0; half < 2; half++) {
                const int row = r0 + half * 8;
                float v0 = acc[mt][nt][half * 2]     + b0;
                float v1 = acc[mt][nt][half * 2 + 1] + b1;
                if (widx == 0) {
                    v0 = __expf(fminf(fmaxf(v0, -60.f), 30.f));
                    v1 = __expf(fminf(fmaxf(v1, -60.f), 30.f));
                } else if (widx == 2) {
                    v0 = __fdividef(1.f, 1.f + __expf(-v0));
                    v1 = __fdividef(1.f, 1.f + __expf(-v1));
                } else if (widx == 3) {
                    const float gm = gamma[row & (TT - 1)];
                    v0 *= gm; v1 *= gm;
                }
                *(float2*)(out + (size_t)row * NA + cb) = make_float2(v0, v1);
            }
        }
    }
}

// ---------------- chunked linear scan (1 channel/thread) ----------------
__global__ __launch_bounds__(256)
void pass_scan_local(const float* __restrict__ time_w,
                     const float* __restrict__ time_alpha)
{
    const int n = blockIdx.x * 256 + threadIdx.x;
    const int j = blockIdx.y;
    const int b = blockIdx.z;
    const int h = n >> 4;
    const float wlast = time_w[h * CTX + CTX - 1];
    const float ratio = time_w[h * CTX + CTX - 2] / wlast;
    float S = 0.f, ks = 0.f;
    const size_t base = ((size_t)(b * TT + j * CL)) * NA + n;
    const float* al = time_alpha + h * CTX + j * CL;
#pragma unroll 8
    for (int u = 0; u < CL; u++) {
        const float kk = g_k[base + (size_t)u * NA];
        const float vv = g_v[base + (size_t)u * NA];
        S  = fmaf(S, ratio, wlast * al[u] * kk * vv);
        ks += kk;
    }
    const int o = (b * NC + j) * NA + n;
    g_Send[o] = S;
    g_Ksum[o] = ks;
}

// carry: batched-load exclusive scan across the NC chunk end-states.
__global__ __launch_bounds__(128)
void pass_scan_carry(const float* __restrict__ time_w)
{
    const int idx = blockIdx.x * 128 + threadIdx.x;   // BB*NA threads
    const int n = idx & (NA - 1);
    const int b = idx >> 10;
    const int h = n >> 4;
    const float ratio = time_w[h * CTX + CTX - 2] / time_w[h * CTX + CTX - 1];
    float rL = ratio;
#pragma unroll
    for (int i = 0; i < 5; i++) rL *= rL;   // ratio^32 (CL=32)

    const float* ps = g_Send + (size_t)(b * NC) * NA + n;
    const float* pk = g_Ksum + (size_t)(b * NC) * NA + n;
    float se[NC], ku[NC];
#pragma unroll
    for (int j = 0; j < NC; j++) {          // independent loads, batched
        se[j] = ps[(size_t)j * NA];
        ku[j] = pk[(size_t)j * NA];
    }
    float cS = 0.f, cK = 0.f;
#pragma unroll
    for (int j = 0; j < NC; j++) {          // register scan
        const float ns = cS * rL + se[j];
        const float nk = cK + ku[j];
        se[j] = cS; ku[j] = cK;             // exclusive prefix in-place
        cS = ns; cK = nk;
    }
    float* qs = g_cS + (size_t)(b * NC) * NA + n;
    float* qk = g_cK + (size_t)(b * NC) * NA + n;
#pragma unroll
    for (int j = 0; j < NC; j++) {
        qs[(size_t)j * NA] = se[j];
        qk[(size_t)j * NA] = ku[j];
    }
}

// final: rwkv = sigmoid(r)*beta*S/ks, written as fp16 fragment-packed A tiles (into g_Ah)
__global__ __launch_bounds__(256)
void pass_scan_final(const float* __restrict__ time_w,
                     const float* __restrict__ time_alpha,
                     const float* __restrict__ time_beta)
{
    const int n = blockIdx.x * 256 + threadIdx.x;   // K-channel of the Wo GEMM
    const int j = blockIdx.y;
    const int b = blockIdx.z;
    const int h = n >> 4;
    const float wlast = time_w[h * CTX + CTX - 1];
    const float ratio = time_w[h * CTX + CTX - 2] / wlast;
    const int o = (b * NC + j) * NA + n;
    float S  = g_cS[o];
    float ks = g_cK[o];
    const size_t base = ((size_t)(b * TT + j * CL)) * NA + n;
    const float* al = time_alpha + h * CTX + j * CL;
    const float* be = time_beta  + h * CTX + j * CL;
    // channel-derived invariants of the fp16 fragment address
    const int tk    = n >> 6;           // k64 tile column
    const int kp    = n & 63;
    const int s_k   = kp >> 4;          // k16 group
    const int kk    = kp & 15;
    const int lanek = (kk & 7) >> 1;    // lane bits from k
    const int bytek = kk & 1;           // which half of the fp16x2
    const int slotk = (kk >= 8) ? 2 : 0;
#pragma unroll 8
    for (int u = 0; u < CL; u++) {
        const size_t off = base + (size_t)u * NA;
        const float kv = g_k[off];
        const float vv = g_v[off];
        const float sr = g_r[off];
        S  = fmaf(S, ratio, wlast * al[u] * kv * vv);
        ks += kv;
        const float val = sr * be[u] * __fdividef(S, ks);
        const int tg    = j * CL + u;   // time index = M row
        const int tile  = (b * 8 + (tg >> 7)) * 16 + tk;
        const int mf    = (tg & 127) >> 4;
        const int rm    = tg & 15;
        const int slot  = (rm >> 3) + slotk;
        const int lane  = (rm & 7) * 4 + lanek;
        const int g     = s_k * 8 + mf;
        *(__half*)((char*)g_Ah + (size_t)tile * ATILE_B
                   + (size_t)(g * 32 + lane) * 16 + slot * 4 + bytek * 2)
            = __float2half_rn(val);
    }
}

// ---------------- launch ----------------
extern "C" void kernel_launch(void* const* d_in, const int* in_sizes, int n_in,
                              void* d_out, int out_size)
{
    const float* x          = (const float*)d_in[0];
    const float* time_w     = (const float*)d_in[1];
    const float* time_alpha = (const float*)d_in[2];
    const float* time_beta  = (const float*)d_in[3];
    const float* time_gamma = (const float*)d_in[4];
    const float* Wk = (const float*)d_in[5];
    const float* bk = (const float*)d_in[6];
    const float* Wv = (const float*)d_in[7];
    const float* bv = (const float*)d_in[8];
    const float* Wr = (const float*)d_in[9];
    const float* br = (const float*)d_in[10];
    const float* Wo = (const float*)d_in[11];
    const float* bo = (const float*)d_in[12];
    float* out = (float*)d_out;

    cudaFuncSetAttribute(gemm_h, cudaFuncAttributeMaxDynamicSharedMemorySize, SMEMT);

    // merged operand conversions (A path + B path in one launch)
    conv_all<<<4096, 256>>>(x, Wk, Wv, Wr, Wo);

    // fused K/V/R projections (fp16, CTA 256x128)
    gemm_h<<<dim3(24, 16), 256, SMEMT>>>(-1, bk, bv, br, bo, time_gamma, out);

    // chunked linear recurrence; writes rwkv into g_Ah (fp16 fragment layout)
    pass_scan_local <<<dim3(4, NC, BB), 256>>>(time_w, time_alpha);
    pass_scan_carry <<<(BB * NA) / 128, 128>>>(time_w);
    pass_scan_final <<<dim3(4, NC, BB), 256>>>(time_w, time_alpha, time_beta);

    // output projection (fp16) with gamma epilogue
    gemm_h<<<dim3(8, 16), 256, SMEMT>>>(3, bk, bv, br, bo, time_gamma, out);
}

// round 13
// speedup vs baseline: 2.4146x; 1.0258x over previous
#include <cuda_runtime.h>
#include <cuda_fp16.h>
#include <math.h>
#include <stdint.h>

// ---------------- problem constants ----------------
#define BB   4
#define TT   1024
#define HID  1024
#define NA   1024
#define CTX  1024
#define NC   32
#define CL   32

// ---------------- GEMM tiling ----------------
// CTA tile 128(M) x 128(N), K-chunk 64, 8 warps (4M x 2N), warp tile 32x64, occ 2.
#define ATILE_H   8192      // one 128x64 fp16 tile = 16KB
#define ATILE_B   16384
#define STG       32768     // stage: 1 A tile + 1 B tile
#define NSTAGE    3
#define SMEMT     (1024 + NSTAGE*STG)

// ---------------- static scratch ----------------
__device__ float g_k[BB*TT*NA];
__device__ float g_v[BB*TT*NA];
__device__ float g_r[BB*TT*NA];
__device__ float g_Send[BB*NC*NA];
__device__ float g_Ksum[BB*NC*NA];
__device__ float g_cS[BB*NC*NA];
__device__ float g_cK[BB*NC*NA];
// fp16 fragment-packed operands (A reused: xs for KVR, then rwkv for Wo)
__device__ __align__(16) __half g_Ah[BB*TT*HID];   // 512 tiles of 128x64
__device__ __align__(16) __half g_Wh[4*HID*NA];    // 4 weights x 128 tiles

// ---------------- ptx helpers (baseline features only) ----------------
__device__ __forceinline__ uint32_t smem_u32(const void* p) {
    uint32_t a;
    asm("{ .reg .u64 t; cvta.to.shared.u64 t, %1; cvt.u32.u64 %0, t; }" : "=r"(a) : "l"(p));
    return a;
}
#define MBAR_INIT(a, c) \
    asm volatile("mbarrier.init.shared.b64 [%0], %1;" :: "r"(a), "r"(c) : "memory")
#define MBAR_EXPECT_TX(a, b) \
    asm volatile("mbarrier.arrive.expect_tx.shared.b64 _, [%0], %1;" :: "r"(a), "r"(b) : "memory")
#define MBAR_ARRIVE(a) \
    asm volatile("mbarrier.arrive.shared.b64 _, [%0];" :: "r"(a) : "memory")
#define MBAR_WAIT(a, ph) do { \
    asm volatile("{\n\t.reg .pred P;\n\tWL%=:\n\t" \
        "mbarrier.try_wait.parity.acquire.cta.shared::cta.b64 P, [%0], %1, 0x989680;\n\t" \
        "@P bra.uni WD%=;\n\tbra.uni WL%=;\n\tWD%=:\n\t}" \
        :: "r"(a), "r"(ph) : "memory"); } while (0)

__device__ __forceinline__ void bulk_ldg(uint32_t dst, const void* src, uint32_t bytes, uint32_t mbar) {
    asm volatile("cp.async.bulk.shared::cluster.global.mbarrier::complete_tx::bytes [%0], [%1], %2, [%3];"
        :: "r"(dst), "l"((unsigned long long)__cvta_generic_to_global(src)), "r"(bytes), "r"(mbar) : "memory");
}
__device__ __forceinline__ void mma16816h(float* d, const uint32_t* a, const uint32_t* b) {
    asm volatile("mma.sync.aligned.m16n8k16.row.col.f32.f16.f16.f32 "
        "{%0,%1,%2,%3}, {%4,%5,%6,%7}, {%8,%9}, {%0,%1,%2,%3};"
        : "+f"(d[0]), "+f"(d[1]), "+f"(d[2]), "+f"(d[3])
        : "r"(a[0]), "r"(a[1]), "r"(a[2]), "r"(a[3]), "r"(b[0]), "r"(b[1]));
}
__device__ __forceinline__ uint32_t h2(float a, float b) {
    __half2 t = __floats2half2_rn(a, b);
    return *(uint32_t*)&t;
}

// ---------------- conversion: SMEM-staged, coalesced ----------------
// blocks 0..511: A path (xs tiles).  512..1023: W path.
// A frag map (m16n8k16.f16): cell(g = s*8+mf, l) = 16B {a0,a1,a2,a3}
// B pair-packed: cell(gp = s*8+fp, l) = {b0(nt=2fp), b1(nt=2fp), b0(nt=2fp+1), b1(nt=2fp+1)}
__global__ __launch_bounds__(256)
void conv_all(const float* __restrict__ x,
              const float* __restrict__ Wk, const float* __restrict__ Wv,
              const float* __restrict__ Wr, const float* __restrict__ Wo)
{
    const int tid = threadIdx.x;
    if (blockIdx.x < 512) {
        // ---- A path: tile = tm*16 + tk, 128 rows (time) x 64 cols (k) ----
        __shared__ float sx[128][66];
        const int tile = blockIdx.x;
        const int tm = tile >> 4, tk = tile & 15;
        const int rr = tid >> 4;             // 16 rows per iter
        const int cg = (tid & 15) * 4;
#pragma unroll
        for (int it = 0; it < 8; it++) {
            const int r = it * 16 + rr;
            const int m = tm * 128 + r;
            const int k = tk * 64 + cg;
            const int t = m & (TT - 1);
            float4 v;
            if (k < HID / 2) {
                if (t > 0) v = *(const float4*)(x + (size_t)(m - 1) * HID + k);
                else       v = make_float4(0.f, 0.f, 0.f, 0.f);
            } else {
                v = *(const float4*)(x + (size_t)m * HID + k);
            }
            sx[r][cg] = v.x; sx[r][cg + 1] = v.y; sx[r][cg + 2] = v.z; sx[r][cg + 3] = v.w;
        }
        __syncthreads();
#pragma unroll
        for (int q = 0; q < 4; q++) {
            const int cell = q * 256 + tid;      // cell = g*32 + l
            const int l = cell & 31, g = cell >> 5;
            const int s = g >> 3, mf = g & 7;
            const int r0 = mf * 16 + (l >> 2);
            const int c0 = s * 16 + (l & 3) * 2;
            uint4 qq;
            qq.x = h2(sx[r0][c0],         sx[r0][c0 + 1]);
            qq.y = h2(sx[r0 + 8][c0],     sx[r0 + 8][c0 + 1]);
            qq.z = h2(sx[r0][c0 + 8],     sx[r0][c0 + 9]);
            qq.w = h2(sx[r0 + 8][c0 + 8], sx[r0 + 8][c0 + 9]);
            *(uint4*)((char*)g_Ah + (size_t)tile * ATILE_B + (size_t)cell * 16) = qq;
        }
    } else {
        // ---- W path: tile = widx*128 + tn*16 + tk, 64 rows (k) x 128 cols (n) ----
        __shared__ float sw[64][130];
        const int tile = blockIdx.x - 512;
        const int widx = tile >> 7;
        const int rem = tile & 127;
        const int tn = rem >> 4, tk = rem & 15;
        const float* W = (widx == 0) ? Wk : (widx == 1) ? Wv : (widx == 2) ? Wr : Wo;
        const int rr = tid >> 5;             // 8 rows per iter
        const int cg = (tid & 31) * 4;
#pragma unroll
        for (int it = 0; it < 8; it++) {
            const int r = it * 8 + rr;
            const int k = tk * 64 + r;
            const int ne = tn * 128 + cg;
            const float4 v = *(const float4*)(W + (size_t)k * NA + ne);
            sw[r][cg] = v.x; sw[r][cg + 1] = v.y; sw[r][cg + 2] = v.z; sw[r][cg + 3] = v.w;
        }
        __syncthreads();
#pragma unroll
        for (int q = 0; q < 4; q++) {
            const int cell = q * 256 + tid;      // cell = gp*32 + l
            const int l = cell & 31, gp = cell >> 5;
            const int s = gp >> 3, fp = gp & 7;
            const int k0 = s * 16 + (l & 3) * 2;
            const int n0 = fp * 16 + (l >> 2);
            uint4 qq;
            qq.x = h2(sw[k0][n0],         sw[k0 + 1][n0]);
            qq.y = h2(sw[k0 + 8][n0],     sw[k0 + 9][n0]);
            qq.z = h2(sw[k0][n0 + 8],     sw[k0 + 1][n0 + 8]);
            qq.w = h2(sw[k0 + 8][n0 + 8], sw[k0 + 9][n0 + 8]);
            *(uint4*)((char*)g_Wh + (size_t)tile * ATILE_B + (size_t)cell * 16) = qq;
        }
    }
}

// ---------------- fp16 GEMM: C[4096, 1024-slice] = A @ W (+bias, +act) ----------------
// CTA 128x128, warp tile 32x64, occupancy 2.
// widx: 0=K(exp-clip) 1=V 2=R(sigmoid) 3=Wo(*gamma, ->obuf)
__global__ __launch_bounds__(256, 2)
void gemm_h(int widx_fixed,
            const float* __restrict__ bk, const float* __restrict__ bv,
            const float* __restrict__ br, const float* __restrict__ bo,
            const float* __restrict__ gamma, float* __restrict__ obuf)
{
    extern __shared__ char smem_raw[];
    char* smem_al = (char*)(((uintptr_t)smem_raw + 1023) & ~(uintptr_t)1023);
    const uint32_t sb = smem_u32(smem_al);
    const int tid = threadIdx.x, l = tid & 31, w = tid >> 5;
    const int wm = w & 3, wn = w >> 2;        // 4 M-warps x 2 N-warps
    int widx, tn;
    if (widx_fixed >= 0) { widx = widx_fixed; tn = blockIdx.x; }
    else                 { widx = blockIdx.x >> 3; tn = blockIdx.x & 7; }
    const int tm = blockIdx.y;                // 32 tiles of 128 rows

    if (tid == 0) {
#pragma unroll
        for (int s = 0; s < NSTAGE; s++) {
            MBAR_INIT(sb + 8 * s, 1);
            MBAR_INIT(sb + 64 + 8 * s, 256);
        }
    }
    __syncthreads();

    const __half* A  = g_Ah + ((size_t)tm * 16) * ATILE_H;
    const __half* Bw = g_Wh + ((size_t)(widx * 8 + tn) * 16) * ATILE_H;

    if (tid == 0) {
#pragma unroll
        for (int c = 0; c < NSTAGE; c++) {
            const uint32_t st = sb + 1024 + c * STG;
            MBAR_EXPECT_TX(sb + 8 * c, STG);
            bulk_ldg(st,         A  + (size_t)c * ATILE_H, ATILE_B, sb + 8 * c);
            bulk_ldg(st + 16384, Bw + (size_t)c * ATILE_H, ATILE_B, sb + 8 * c);
        }
    }

    float acc[2][8][4];
#pragma unroll
    for (int i = 0; i < 2; i++)
#pragma unroll
        for (int j = 0; j < 8; j++)
#pragma unroll
            for (int q = 0; q < 4; q++) acc[i][j][q] = 0.f;

    // A: warp wm owns m16 frags mf = wm*2 + mt
    const uint32_t a_wbase = ((uint32_t)(wm * 2) * 32 + l) * 16;
    // B: gp = s*8 + wn*4 + ntp
    const uint32_t b_wbase = 16384u + ((uint32_t)(wn * 4) * 32 + l) * 16;

    for (int c = 0; c < 16; c++) {
        const int s = c % NSTAGE;
        const uint32_t par = (uint32_t)((c / NSTAGE) & 1);
        MBAR_WAIT(sb + 8 * s, par);
        const char* stp = smem_al + 1024 + s * STG;
        const char* ap = stp + a_wbase;
        const char* bp = stp + b_wbase;
#pragma unroll 2
        for (int ks = 0; ks < 4; ks++) {      // k16 steps within the 64-chunk
            uint4 Aq[2], Bq[4];
#pragma unroll
            for (int mt = 0; mt < 2; mt++)
                Aq[mt] = *(const uint4*)(ap + (uint32_t)(ks * 8 + mt) * 512);
#pragma unroll
            for (int ntp = 0; ntp < 4; ntp++)
                Bq[ntp] = *(const uint4*)(bp + (uint32_t)(ks * 8 + ntp) * 512);
#pragma unroll
            for (int mt = 0; mt < 2; mt++) {
                const uint32_t Af[4] = {Aq[mt].x, Aq[mt].y, Aq[mt].z, Aq[mt].w};
#pragma unroll
                for (int ntp = 0; ntp < 4; ntp++) {
                    const uint32_t B0[2] = {Bq[ntp].x, Bq[ntp].y};
                    const uint32_t B1[2] = {Bq[ntp].z, Bq[ntp].w};
                    mma16816h(acc[mt][2 * ntp],     Af, B0);
                    mma16816h(acc[mt][2 * ntp + 1], Af, B1);
                }
            }
        }
        MBAR_ARRIVE(sb + 64 + 8 * s);
        if (tid == 0 && c + NSTAGE < 16) {
            MBAR_WAIT(sb + 64 + 8 * s, par);
            const int cc = c + NSTAGE;
            const uint32_t st = sb + 1024 + s * STG;
            MBAR_EXPECT_TX(sb + 8 * s, STG);
            bulk_ldg(st,         A  + (size_t)cc * ATILE_H, ATILE_B, sb + 8 * s);
            bulk_ldg(st + 16384, Bw + (size_t)cc * ATILE_H, ATILE_B, sb + 8 * s);
        }
    }

    // ---- epilogue ----
    const float* bias = (widx == 0) ? bk : (widx == 1) ? bv : (widx == 2) ? br : bo;
    float* out = (widx == 0) ? g_k : (widx == 1) ? g_v : (widx == 2) ? g_r : obuf;
    const int mrow_base = tm * 128 + wm * 32;
    const int col_base  = tn * 128 + wn * 64;
#pragma unroll
    for (int mt = 0; mt < 2; mt++) {
#pragma unroll
        for (int nt = 0; nt < 8; nt++) {
            const int r0 = mrow_base + mt * 16 + (l >> 2);
            const int cb = col_base + nt * 8 + (l & 3) * 2;
            const float b0 = bias[cb], b1 = bias[cb + 1];
#pragma unroll
            for (int half = 0; half < 2; half++) {
                const int row = r0 + half * 8;
                float v0 = acc[mt][nt][half * 2]     + b0;
                float v1 = acc[mt][nt][half * 2 + 1] + b1;
                if (widx == 0) {
                    v0 = __expf(fminf(fmaxf(v0, -60.f), 30.f));
                    v1 = __expf(fminf(fmaxf(v1, -60.f), 30.f));
                } else if (widx == 2) {
                    v0 = __fdividef(1.f, 1.f + __expf(-v0));
                    v1 = __fdividef(1.f, 1.f + __expf(-v1));
                } else if (widx == 3) {
                    const float gm = gamma[row & (TT - 1)];
                    v0 *= gm; v1 *= gm;
                }
                *(float2*)(out + (size_t)row * NA + cb) = make_float2(v0, v1);
            }
        }
    }
}

// ---------------- chunked linear scan (1 channel/thread) ----------------
__global__ __launch_bounds__(256)
void pass_scan_local(const float* __restrict__ time_w,
                     const float* __restrict__ time_alpha)
{
    const int n = blockIdx.x * 256 + threadIdx.x;
    const int j = blockIdx.y;
    const int b = blockIdx.z;
    const int h = n >> 4;
    const float wlast = time_w[h * CTX + CTX - 1];
    const float ratio = time_w[h * CTX + CTX - 2] / wlast;
    float S = 0.f, ks = 0.f;
    const size_t base = ((size_t)(b * TT + j * CL)) * NA + n;
    const float* al = time_alpha + h * CTX + j * CL;
#pragma unroll 8
    for (int u = 0; u < CL; u++) {
        const float kk = g_k[base + (size_t)u * NA];
        const float vv = g_v[base + (size_t)u * NA];
        S  = fmaf(S, ratio, wlast * al[u] * kk * vv);
        ks += kk;
    }
    const int o = (b * NC + j) * NA + n;
    g_Send[o] = S;
    g_Ksum[o] = ks;
}

// carry: batched-load exclusive scan across the NC chunk end-states.
__global__ __launch_bounds__(128)
void pass_scan_carry(const float* __restrict__ time_w)
{
    const int idx = blockIdx.x * 128 + threadIdx.x;   // BB*NA threads
    const int n = idx & (NA - 1);
    const int b = idx >> 10;
    const int h = n >> 4;
    const float ratio = time_w[h * CTX + CTX - 2] / time_w[h * CTX + CTX - 1];
    float rL = ratio;
#pragma unroll
    for (int i = 0; i < 5; i++) rL *= rL;   // ratio^32 (CL=32)

    const float* ps = g_Send + (size_t)(b * NC) * NA + n;
    const float* pk = g_Ksum + (size_t)(b * NC) * NA + n;
    float se[NC], ku[NC];
#pragma unroll
    for (int j = 0; j < NC; j++) {          // independent loads, batched
        se[j] = ps[(size_t)j * NA];
        ku[j] = pk[(size_t)j * NA];
    }
    float cS = 0.f, cK = 0.f;
#pragma unroll
    for (int j = 0; j < NC; j++) {          // register scan
        const float ns = cS * rL + se[j];
        const float nk = cK + ku[j];
        se[j] = cS; ku[j] = cK;             // exclusive prefix in-place
        cS = ns; cK = nk;
    }
    float* qs = g_cS + (size_t)(b * NC) * NA + n;
    float* qk = g_cK + (size_t)(b * NC) * NA + n;
#pragma unroll
    for (int j = 0; j < NC; j++) {
        qs[(size_t)j * NA] = se[j];
        qk[(size_t)j * NA] = ku[j];
    }
}

// final: rwkv = sigmoid(r)*beta*S/ks, written as fp16 fragment-packed A tiles (into g_Ah)
__global__ __launch_bounds__(256)
void pass_scan_final(const float* __restrict__ time_w,
                     const float* __restrict__ time_alpha,
                     const float* __restrict__ time_beta)
{
    const int n = blockIdx.x * 256 + threadIdx.x;   // K-channel of the Wo GEMM
    const int j = blockIdx.y;
    const int b = blockIdx.z;
    const int h = n >> 4;
    const float wlast = time_w[h * CTX + CTX - 1];
    const float ratio = time_w[h * CTX + CTX - 2] / wlast;
    const int o = (b * NC + j) * NA + n;
    float S  = g_cS[o];
    float ks = g_cK[o];
    const size_t base = ((size_t)(b * TT + j * CL)) * NA + n;
    const float* al = time_alpha + h * CTX + j * CL;
    const float* be = time_beta  + h * CTX + j * CL;
    // channel-derived invariants of the fp16 fragment address
    const int tk    = n >> 6;           // k64 tile column
    const int kp    = n & 63;
    const int s_k   = kp >> 4;          // k16 group
    const int kk    = kp & 15;
    const int lanek = (kk & 7) >> 1;    // lane bits from k
    const int bytek = kk & 1;           // which half of the fp16x2
    const int slotk = (kk >= 8) ? 2 : 0;
#pragma unroll 8
    for (int u = 0; u < CL; u++) {
        const size_t off = base + (size_t)u * NA;
        const float kv = g_k[off];
        const float vv = g_v[off];
        const float sr = g_r[off];
        S  = fmaf(S, ratio, wlast * al[u] * kv * vv);
        ks += kv;
        const float val = sr * be[u] * __fdividef(S, ks);
        const int tg    = j * CL + u;   // time index = M row
        const int tile  = (b * 8 + (tg >> 7)) * 16 + tk;
        const int mf    = (tg & 127) >> 4;
        const int rm    = tg & 15;
        const int slot  = (rm >> 3) + slotk;
        const int lane  = (rm & 7) * 4 + lanek;
        const int g     = s_k * 8 + mf;
        *(__half*)((char*)g_Ah + (size_t)tile * ATILE_B
                   + (size_t)(g * 32 + lane) * 16 + slot * 4 + bytek * 2)
            = __float2half_rn(val);
    }
}

// ---------------- launch ----------------
extern "C" void kernel_launch(void* const* d_in, const int* in_sizes, int n_in,
                              void* d_out, int out_size)
{
    const float* x          = (const float*)d_in[0];
    const float* time_w     = (const float*)d_in[1];
    const float* time_alpha = (const float*)d_in[2];
    const float* time_beta  = (const float*)d_in[3];
    const float* time_gamma = (const float*)d_in[4];
    const float* Wk = (const float*)d_in[5];
    const float* bk = (const float*)d_in[6];
    const float* Wv = (const float*)d_in[7];
    const float* bv = (const float*)d_in[8];
    const float* Wr = (const float*)d_in[9];
    const float* br = (const float*)d_in[10];
    const float* Wo = (const float*)d_in[11];
    const float* bo = (const float*)d_in[12];
    float* out = (float*)d_out;

    cudaFuncSetAttribute(gemm_h, cudaFuncAttributeMaxDynamicSharedMemorySize, SMEMT);

    // SMEM-staged operand conversions (A path + W path in one launch)
    conv_all<<<1024, 256>>>(x, Wk, Wv, Wr, Wo);

    // fused K/V/R projections (fp16, CTA 128x128, occ 2)
    gemm_h<<<dim3(24, 32), 256, SMEMT>>>(-1, bk, bv, br, bo, time_gamma, out);

    // chunked linear recurrence; writes rwkv into g_Ah (fp16 fragment layout)
    pass_scan_local <<<dim3(4, NC, BB), 256>>>(time_w, time_alpha);
    pass_scan_carry <<<(BB * NA) / 128, 128>>>(time_w);
    pass_scan_final <<<dim3(4, NC, BB), 256>>>(time_w, time_alpha, time_beta);

    // output projection (fp16) with gamma epilogue
    gemm_h<<<dim3(8, 32), 256, SMEMT>>>(3, bk, bv, br, bo, time_gamma, out);
}